// round 11
// baseline (speedup 1.0000x reference)
#include <cuda_runtime.h>
#include <cstdint>

#define TT 1024
#define DD 64
#define HH 256
#define OO 128
#define THREADS 512

typedef unsigned long long ull;

// smem float offsets (dynamic, 75792 B)
#define OFF_WX1 0        // [64][64]    wx1[k*64 + jloc]
#define OFF_H1  4096     // [3][1024]   triple-buffered h1[col*4 + m]
#define OFF_H2  7168     // [3][1024]   triple-buffered h2
#define OFF_XT  10240    // [2][256]    xT[p][k*4 + m]
#define OFF_SCR 10752    // [16][512]   partials: [warp][j] j<256:h1, j>=256:h2
#define OFF_MBAR 18944   // 1 x u64 mbarrier (+pad)
#define SMEM_FLOATS 18948
#define SMEM_BYTES (SMEM_FLOATS * 4)
#define MBAR_B (OFF_MBAR * 4)

__device__ __forceinline__ ull ffma2(ull a, ull b, ull c) {
    ull d; asm("fma.rn.f32x2 %0,%1,%2,%3;" : "=l"(d) : "l"(a), "l"(b), "l"(c)); return d;
}
__device__ __forceinline__ ull pk2(float lo, float hi) {
    ull d; asm("mov.b64 %0,{%1,%2};" : "=l"(d) : "f"(lo), "f"(hi)); return d;
}
__device__ __forceinline__ void up2(ull a, float& lo, float& hi) {
    asm("mov.b64 {%0,%1},%2;" : "=f"(lo), "=f"(hi) : "l"(a));
}
__device__ __forceinline__ uint32_t s2u(const void* p) {
    uint32_t a;
    asm("{.reg .u64 t; cvta.to.shared.u64 t, %1; cvt.u32.u64 %0, t;}" : "=r"(a) : "l"(p));
    return a;
}
__device__ __forceinline__ void mbar_init(uint32_t m, uint32_t cnt) {
    asm volatile("mbarrier.init.shared.b64 [%0], %1;" :: "r"(m), "r"(cnt) : "memory");
}
__device__ __forceinline__ void mbar_expect(uint32_t m, uint32_t bytes) {
    asm volatile("mbarrier.arrive.expect_tx.shared.b64 _, [%0], %1;" :: "r"(m), "r"(bytes) : "memory");
}
__device__ __forceinline__ void mbar_wait(uint32_t m, uint32_t parity) {
    asm volatile(
        "{\n\t.reg .pred P;\n"
        "W%=:\n\t"
        "mbarrier.try_wait.parity.acquire.cta.shared::cta.b64 P, [%0], %1, 0x989680;\n\t"
        "@!P bra W%=;\n\t}"
        :: "r"(m), "r"(parity) : "memory");
}
__device__ __forceinline__ void bulk_dsmem(uint32_t dst, uint32_t src, uint32_t bytes,
                                           uint32_t dmbar) {
    asm volatile(
        "cp.async.bulk.shared::cluster.shared::cta.mbarrier::complete_tx::bytes "
        "[%0], [%1], %2, [%3];"
        :: "r"(dst), "r"(src), "r"(bytes), "r"(dmbar) : "memory");
}
#define FENCE_ASYNC() asm volatile("fence.proxy.async.shared::cta;" ::: "memory")
#define CLUSTER_SYNC() do { \
    asm volatile("barrier.cluster.arrive.aligned;" ::: "memory"); \
    asm volatile("barrier.cluster.wait.aligned;" ::: "memory"); } while (0)

// 16 k-steps vs register weights; hv = broadcast float4 rows h[k][m0..3] (R4-proven)
__device__ __forceinline__ void accum16(const float (&wA)[16], const float (&wB)[16],
                                        const float4* __restrict__ hv,
                                        ull& aA01, ull& aA23, ull& aB01, ull& aB23) {
#pragma unroll
    for (int i = 0; i < 16; i++) {
        float4 h4 = hv[i];
        ull H01 = pk2(h4.x, h4.y), H23 = pk2(h4.z, h4.w);
        ull wdA = pk2(wA[i], wA[i]);
        ull wdB = pk2(wB[i], wB[i]);
        aA01 = ffma2(wdA, H01, aA01);
        aA23 = ffma2(wdA, H23, aA23);
        aB01 = ffma2(wdB, H01, aB01);
        aB23 = ffma2(wdB, H23, aB23);
    }
}

// 4 k-steps of x-projection; warp w covers k in [4w,4w+4). (R4-proven)
__device__ __forceinline__ void accum_x(const float* __restrict__ smw, int w, int lane,
                                        const float4* __restrict__ xv,
                                        ull& aA01, ull& aA23, ull& aB01, ull& aB23) {
#pragma unroll
    for (int i = 0; i < 4; i++) {
        float2 wv = *(const float2*)(smw + (4 * w + i) * 64 + 2 * lane);
        float4 h4 = xv[i];
        ull H01 = pk2(h4.x, h4.y), H23 = pk2(h4.z, h4.w);
        ull wdA = pk2(wv.x, wv.x);
        ull wdB = pk2(wv.y, wv.y);
        aA01 = ffma2(wdA, H01, aA01);
        aA23 = ffma2(wdA, H23, aA23);
        aB01 = ffma2(wdB, H01, aB01);
        aB23 = ffma2(wdB, H23, aB23);
    }
}

__device__ __forceinline__ void sts_partials(float* sm, int w, int lane, int half,
                                             ull a01, ull a23, ull b01, ull b23) {
    float4 pA, pB;
    up2(a01, pA.x, pA.y); up2(a23, pA.z, pA.w);
    up2(b01, pB.x, pB.y); up2(b23, pB.z, pB.w);
    float4* base = (float4*)(sm + OFF_SCR + w * 512 + half * 256 + 8 * lane);
    base[0] = pA;
    base[1] = pB;
}

__global__ void __launch_bounds__(THREADS, 1) __cluster_dims__(4, 1, 1)
rnn_kernel(const float* __restrict__ x, const float* __restrict__ Wx1,
           const float* __restrict__ Wh1, const float* __restrict__ b1,
           const float* __restrict__ Wx2, const float* __restrict__ Wh2,
           const float* __restrict__ b2, const float* __restrict__ Wd,
           const float* __restrict__ bd, float* __restrict__ out) {
    extern __shared__ float sm[];
    int tid = threadIdx.x;
    int w = tid >> 5, lane = tid & 31;
    uint32_t rank;
    asm("mov.u32 %0, %%cluster_ctarank;" : "=r"(rank));
    int colg = (int)rank * 64;
    int colg4 = colg * 4;
    int bm0 = ((int)blockIdx.x >> 2) * 4;

    // Wx1 slice -> smem (k-major, 64 cols of this CTA)
    for (int i = tid; i < 4096; i += THREADS) {
        int k = i >> 6, jl = i & 63;
        sm[OFF_WX1 + i] = Wx1[k * HH + colg + jl];
    }
    // zero h1[3] + h2[3] + xT (contiguous 4096..10752)
    for (int i = tid; i < 6656; i += THREADS) sm[OFF_H1 + i] = 0.f;

    // recurrent weights -> registers: warp w owns k in [16w,16w+16),
    // lane owns cols {colg+2*lane, colg+2*lane+1}
    float wh1A[16], wh1B[16], wx2A[16], wx2B[16], wh2A[16], wh2B[16];
    {
        const float2* g1 = (const float2*)Wh1;
        const float2* g2 = (const float2*)Wx2;
        const float2* g3 = (const float2*)Wh2;
        int cw = (colg >> 1) + lane;
#pragma unroll
        for (int i = 0; i < 16; i++) {
            float2 a = g1[(16 * w + i) * (HH / 2) + cw]; wh1A[i] = a.x; wh1B[i] = a.y;
            float2 b = g2[(16 * w + i) * (HH / 2) + cw]; wx2A[i] = b.x; wx2B[i] = b.y;
            float2 c = g3[(16 * w + i) * (HH / 2) + cw]; wh2A[i] = c.x; wh2B[i] = c.y;
        }
    }
    // per-thread reduce bias: j<256 -> h1 (b1), j>=256 -> h2 (b2)
    float bsel = (tid < 256) ? b1[colg + (tid >> 2)] : b2[colg + ((tid - 256) >> 2)];
    uint32_t su = s2u(sm);
    uint32_t peer[4];
#pragma unroll
    for (int r = 0; r < 4; r++)
        asm("mapa.shared::cluster.u32 %0,%1,%2;" : "=r"(peer[r]) : "r"(su), "r"(r));

    if (tid == 0) mbar_init(su + MBAR_B, 1);
    // stage x(0) -> xT[0], x(1) -> xT[1]
    const size_t xbase = (size_t)(bm0 + (tid & 3)) * TT * DD + (tid >> 2);
    if (tid < 256) {
        sm[OFF_XT + tid] = x[xbase];
        sm[OFF_XT + 256 + tid] = x[xbase + DD];
    }
    __syncthreads();
    CLUSTER_SYNC();   // mbarriers + buffers live before any DSMEM traffic

    // ---- pre-phase: h1(0) = tanh(Wx1 x(0) + b1) into h1 buffer 0 ----
    {
        ull a01 = 0, a23 = 0, b01 = 0, b23 = 0;
        accum_x(sm + OFF_WX1, w, lane, (const float4*)(sm + OFF_XT) + 4 * w,
                a01, a23, b01, b23);
        sts_partials(sm, w, lane, 0, a01, a23, b01, b23);
        __syncthreads();
        if (tid == 0) mbar_expect(su + MBAR_B, 3072);
        if (tid < 256) {
            const float* s0 = sm + OFF_SCR + tid;
            float u0 = s0[0] + s0[8 * 512], u1 = s0[1 * 512] + s0[9 * 512];
            float u2 = s0[2 * 512] + s0[10 * 512], u3 = s0[3 * 512] + s0[11 * 512];
            float u4 = s0[4 * 512] + s0[12 * 512], u5 = s0[5 * 512] + s0[13 * 512];
            float u6 = s0[6 * 512] + s0[14 * 512], u7 = s0[7 * 512] + s0[15 * 512];
            u0 += u4; u1 += u5; u2 += u6; u3 += u7;
            sm[OFF_H1 + colg4 + tid] = tanhf(((u0 + u2) + (u1 + u3)) + bsel);
        }
        __syncthreads();
        if (tid < 3) {
            FENCE_ASYNC();
            uint32_t rr = (rank + 1u + (uint32_t)tid) & 3u;
            uint32_t off = (uint32_t)(OFF_H1 + colg4) * 4u;
            bulk_dsmem(peer[rr] + off, su + off, 1024u, peer[rr] + MBAR_B);
        }
        mbar_wait(su + MBAR_B, 0u);
    }

    // ---- main loop: one phase per step; triple-buffered h1/h2 ----
    // iter t: reads h1(t) [buf i0], h2(t-1) [buf i2], x(t+1) [xT[(t+1)&1]];
    // writes h1(t+1) [buf i1], h2(t) [buf i0]; prefetches x(t+2) -> xT[t&1].
    int i0 = 0, i1 = 1, i2 = 2;
    uint32_t par = 1;
#pragma unroll 1
    for (int t = 0; t < TT; t++) {
        if (tid == 0) mbar_expect(su + MBAR_B, 6144);
        float xreg = 0.f;
        bool pf = (t + 2 < TT) && (tid < 256);
        if (pf) xreg = x[xbase + (size_t)(t + 2) * DD];

        // h2(t) partials -> scratch upper half
        {
            ull c01 = 0, c23 = 0, d01 = 0, d23 = 0;
            accum16(wx2A, wx2B, (const float4*)(sm + OFF_H1 + i0 * 1024) + 16 * w,
                    c01, c23, d01, d23);
            accum16(wh2A, wh2B, (const float4*)(sm + OFF_H2 + i2 * 1024) + 16 * w,
                    c01, c23, d01, d23);
            sts_partials(sm, w, lane, 1, c01, c23, d01, d23);
        }
        // h1(t+1) partials -> scratch lower half
        {
            ull a01 = 0, a23 = 0, b01 = 0, b23 = 0;
            accum_x(sm + OFF_WX1, w, lane,
                    (const float4*)(sm + OFF_XT + ((t + 1) & 1) * 256) + 4 * w,
                    a01, a23, b01, b23);
            accum16(wh1A, wh1B, (const float4*)(sm + OFF_H1 + i0 * 1024) + 16 * w,
                    a01, a23, b01, b23);
            sts_partials(sm, w, lane, 0, a01, a23, b01, b23);
        }
        __syncthreads();                       // bar A: all partials visible
        if (pf) sm[OFF_XT + (t & 1) * 256 + tid] = xreg;
        {
            const float* s0 = sm + OFF_SCR + tid;
            float u0 = s0[0] + s0[8 * 512], u1 = s0[1 * 512] + s0[9 * 512];
            float u2 = s0[2 * 512] + s0[10 * 512], u3 = s0[3 * 512] + s0[11 * 512];
            float u4 = s0[4 * 512] + s0[12 * 512], u5 = s0[5 * 512] + s0[13 * 512];
            float u6 = s0[6 * 512] + s0[14 * 512], u7 = s0[7 * 512] + s0[15 * 512];
            u0 += u4; u1 += u5; u2 += u6; u3 += u7;
            float h = tanhf(((u0 + u2) + (u1 + u3)) + bsel);
            int dst = (tid < 256) ? (OFF_H1 + i1 * 1024 + colg4 + tid)
                                  : (OFF_H2 + i0 * 1024 + colg4 + tid - 256);
            sm[dst] = h;
        }
        __syncthreads();                       // bar B: local slices + xT staged
        if (tid < 6) {
            FENCE_ASYNC();
            uint32_t rr = (rank + 1u + ((uint32_t)tid >> 1)) & 3u;
            uint32_t off = (tid & 1) ? (uint32_t)(OFF_H2 + i0 * 1024 + colg4) * 4u
                                     : (uint32_t)(OFF_H1 + i1 * 1024 + colg4) * 4u;
            bulk_dsmem(peer[rr] + off, su + off, 1024u, peer[rr] + MBAR_B);
        }
        mbar_wait(su + MBAR_B, par);
        par ^= 1u;
        int tmp = i0; i0 = i1; i1 = i2; i2 = tmp;
    }
    __syncthreads();

    // ---- epilogue: every rank outputs its own batch row ----
    // final h2(1023) lives in h2 buffer 1023%3 == 0
    {
        const float* h2f = sm + OFF_H2;
        int kq = tid >> 7, o = tid & 127;
        float part = 0.f;
#pragma unroll 8
        for (int i = 0; i < 64; i++) {
            int k = kq * 64 + i;
            part += h2f[k * 4 + rank] * Wd[k * OO + o];
        }
        sm[OFF_SCR + kq * 128 + o] = part;
        __syncthreads();
        if (tid < 128) {
            float l = bd[tid] + sm[OFF_SCR + tid] + sm[OFF_SCR + 128 + tid]
                    + sm[OFF_SCR + 256 + tid] + sm[OFF_SCR + 384 + tid];
            sm[OFF_SCR + 512 + tid] = l;
        }
        __syncthreads();
        if (tid < 32) {
            const float* L = sm + OFF_SCR + 512;
            float v0 = L[tid], v1 = L[tid + 32], v2 = L[tid + 64], v3 = L[tid + 96];
            float mx = fmaxf(fmaxf(v0, v1), fmaxf(v2, v3));
#pragma unroll
            for (int s = 16; s; s >>= 1) mx = fmaxf(mx, __shfl_xor_sync(0xffffffffu, mx, s));
            float e0 = __expf(v0 - mx), e1 = __expf(v1 - mx);
            float e2 = __expf(v2 - mx), e3 = __expf(v3 - mx);
            float ssum = e0 + e1 + e2 + e3;
#pragma unroll
            for (int s = 16; s; s >>= 1) ssum += __shfl_xor_sync(0xffffffffu, ssum, s);
            float inv = 1.f / ssum;
            float* orow = out + (size_t)(bm0 + (int)rank) * OO;
            orow[tid] = e0 * inv;
            orow[tid + 32] = e1 * inv;
            orow[tid + 64] = e2 * inv;
            orow[tid + 96] = e3 * inv;
        }
    }
    CLUSTER_SYNC();   // keep cluster alive until all in-flight bulks land
}

extern "C" void kernel_launch(void* const* d_in, const int* in_sizes, int n_in,
                              void* d_out, int out_size) {
    cudaFuncSetAttribute(rnn_kernel, cudaFuncAttributeMaxDynamicSharedMemorySize, SMEM_BYTES);
    rnn_kernel<<<128, THREADS, SMEM_BYTES>>>(
        (const float*)d_in[0], (const float*)d_in[1], (const float*)d_in[2],
        (const float*)d_in[3], (const float*)d_in[4], (const float*)d_in[5],
        (const float*)d_in[6], (const float*)d_in[7], (const float*)d_in[8],
        (float*)d_out);
}

// round 13
// speedup vs baseline: 1.0999x; 1.0999x over previous
#include <cuda_runtime.h>
#include <cstdint>

#define TT 1024
#define DD 64
#define HH 256
#define OO 128
#define THREADS 512

typedef unsigned long long ull;

// smem float offsets (dynamic) — Round-4 layout + 8 per-source mbarriers
#define OFF_WX1 0        // [64][64]   wx1[k*64 + jloc]
#define OFF_H1  4096     // [2][1024]  h1[p][col*4 + m]
#define OFF_H2  6144     // [2][1024]
#define OFF_XT  8192     // [2][256]   xT[p][k*4 + m]
#define OFF_SCR 8704     // [16][256]  reduction scratch
#define OFF_MBAR 12928   // 8 x u64 mbarriers: mb1[0..3], mb2[0..3]
#define SMEM_FLOATS 12944
#define SMEM_BYTES (SMEM_FLOATS * 4)
#define MB1_B (OFF_MBAR * 4)          // mb1[s] = MB1_B + 8*s  (h1 exchange, per source)
#define MB2_B (OFF_MBAR * 4 + 32)     // mb2[s] = MB2_B + 8*s  (h2 exchange, per source)

__device__ __forceinline__ ull ffma2(ull a, ull b, ull c) {
    ull d; asm("fma.rn.f32x2 %0,%1,%2,%3;" : "=l"(d) : "l"(a), "l"(b), "l"(c)); return d;
}
__device__ __forceinline__ ull pk2(float lo, float hi) {
    ull d; asm("mov.b64 %0,{%1,%2};" : "=l"(d) : "f"(lo), "f"(hi)); return d;
}
__device__ __forceinline__ void up2(ull a, float& lo, float& hi) {
    asm("mov.b64 {%0,%1},%2;" : "=f"(lo), "=f"(hi) : "l"(a));
}
__device__ __forceinline__ uint32_t s2u(const void* p) {
    uint32_t a;
    asm("{.reg .u64 t; cvta.to.shared.u64 t, %1; cvt.u32.u64 %0, t;}" : "=r"(a) : "l"(p));
    return a;
}
__device__ __forceinline__ void mbar_init(uint32_t m, uint32_t cnt) {
    asm volatile("mbarrier.init.shared.b64 [%0], %1;" :: "r"(m), "r"(cnt) : "memory");
}
__device__ __forceinline__ void mbar_expect(uint32_t m, uint32_t bytes) {
    asm volatile("mbarrier.arrive.expect_tx.shared.b64 _, [%0], %1;" :: "r"(m), "r"(bytes) : "memory");
}
__device__ __forceinline__ void mbar_wait(uint32_t m, uint32_t parity) {
    asm volatile(
        "{\n\t.reg .pred P;\n"
        "W%=:\n\t"
        "mbarrier.try_wait.parity.acquire.cta.shared::cta.b64 P, [%0], %1, 0x989680;\n\t"
        "@!P bra W%=;\n\t}"
        :: "r"(m), "r"(parity) : "memory");
}
__device__ __forceinline__ void st_async_f32(uint32_t daddr, float v, uint32_t dmbar) {
    asm volatile("st.async.shared::cluster.mbarrier::complete_tx::bytes.f32 [%0], %1, [%2];"
                 :: "r"(daddr), "f"(v), "r"(dmbar) : "memory");
}
#define CLUSTER_SYNC() do { \
    asm volatile("barrier.cluster.arrive.aligned;" ::: "memory"); \
    asm volatile("barrier.cluster.wait.aligned;" ::: "memory"); } while (0)

// 16 k-steps vs register weights; hv = broadcast float4 rows h[k][m0..3] (R4-proven)
__device__ __forceinline__ void accum16(const float (&wA)[16], const float (&wB)[16],
                                        const float4* __restrict__ hv,
                                        ull& aA01, ull& aA23, ull& aB01, ull& aB23) {
#pragma unroll
    for (int i = 0; i < 16; i++) {
        float4 h4 = hv[i];
        ull H01 = pk2(h4.x, h4.y), H23 = pk2(h4.z, h4.w);
        ull wdA = pk2(wA[i], wA[i]);
        ull wdB = pk2(wB[i], wB[i]);
        aA01 = ffma2(wdA, H01, aA01);
        aA23 = ffma2(wdA, H23, aA23);
        aB01 = ffma2(wdB, H01, aB01);
        aB23 = ffma2(wdB, H23, aB23);
    }
}

// 4 k-steps of x-projection; warp w covers k in [4w,4w+4). (R4-proven)
__device__ __forceinline__ void accum_x(const float* __restrict__ smw, int w, int lane,
                                        const float4* __restrict__ xv,
                                        ull& aA01, ull& aA23, ull& aB01, ull& aB23) {
#pragma unroll
    for (int i = 0; i < 4; i++) {
        float2 wv = *(const float2*)(smw + (4 * w + i) * 64 + 2 * lane);
        float4 h4 = xv[i];
        ull H01 = pk2(h4.x, h4.y), H23 = pk2(h4.z, h4.w);
        ull wdA = pk2(wv.x, wv.x);
        ull wdB = pk2(wv.y, wv.y);
        aA01 = ffma2(wdA, H01, aA01);
        aA23 = ffma2(wdA, H23, aA23);
        aB01 = ffma2(wdB, H01, aB01);
        aB23 = ffma2(wdB, H23, aB23);
    }
}

// R4-proven reduce + bias + tanh + f32 st.async broadcast; messages complete
// the PER-SOURCE mbarrier (mb base + 8*rank) on each destination CTA.
__device__ __forceinline__ void reduce_bcast(float* sm, int tid, int w, int lane,
                                             ull aA01, ull aA23, ull aB01, ull aB23,
                                             float bias, int dst_off, int colg,
                                             const uint32_t (&peer)[4], uint32_t mbar_src_b) {
    __syncthreads();                           // prior scratch use complete
    float4 pA, pB;
    up2(aA01, pA.x, pA.y); up2(aA23, pA.z, pA.w);
    up2(aB01, pB.x, pB.y); up2(aB23, pB.z, pB.w);
    float4* base = (float4*)(sm + OFF_SCR + w * 256 + 8 * lane);
    base[0] = pA;                              // outs [8*lane, 8*lane+8) dense
    base[1] = pB;
    __syncthreads();
    if (tid < 256) {
        float s = bias;
#pragma unroll
        for (int qq = 0; qq < 16; qq++) s += sm[OFF_SCR + qq * 256 + tid];
        float h = tanhf(s);
        uint32_t off = (uint32_t)(dst_off + colg * 4 + tid) * 4u;
#pragma unroll
        for (int r = 0; r < 4; r++)
            st_async_f32(peer[r] + off, h, peer[r] + mbar_src_b);
    }
}

__global__ void __launch_bounds__(THREADS, 1) __cluster_dims__(4, 1, 1)
rnn_kernel(const float* __restrict__ x, const float* __restrict__ Wx1,
           const float* __restrict__ Wh1, const float* __restrict__ b1,
           const float* __restrict__ Wx2, const float* __restrict__ Wh2,
           const float* __restrict__ b2, const float* __restrict__ Wd,
           const float* __restrict__ bd, float* __restrict__ out) {
    extern __shared__ float sm[];
    int tid = threadIdx.x;
    int w = tid >> 5, lane = tid & 31;
    uint32_t rank;
    asm("mov.u32 %0, %%cluster_ctarank;" : "=r"(rank));
    int colg = (int)rank * 64;
    int bm0 = ((int)blockIdx.x >> 2) * 4;
    uint32_t src8 = 8u * (uint32_t)(w >> 2);        // this warp's h-source CTA * 8
    bool owner = ((w & 3) == 0) && (lane == 0);     // one poster per source barrier

    // Wx1 slice -> smem (k-major, 64 cols of this CTA)
    for (int i = tid; i < 4096; i += THREADS) {
        int k = i >> 6, jl = i & 63;
        sm[OFF_WX1 + i] = Wx1[k * HH + colg + jl];
    }
    // zero h buffers + xT
    for (int i = tid; i < 4608; i += THREADS) sm[OFF_H1 + i] = 0.f;

    // recurrent weights -> registers: warp w owns k in [16w,16w+16),
    // lane owns cols {colg+2*lane, colg+2*lane+1}
    float wh1A[16], wh1B[16], wx2A[16], wx2B[16], wh2A[16], wh2B[16];
    {
        const float2* g1 = (const float2*)Wh1;
        const float2* g2 = (const float2*)Wx2;
        const float2* g3 = (const float2*)Wh2;
        int cw = (colg >> 1) + lane;
#pragma unroll
        for (int i = 0; i < 16; i++) {
            float2 a = g1[(16 * w + i) * (HH / 2) + cw]; wh1A[i] = a.x; wh1B[i] = a.y;
            float2 b = g2[(16 * w + i) * (HH / 2) + cw]; wx2A[i] = b.x; wx2B[i] = b.y;
            float2 c = g3[(16 * w + i) * (HH / 2) + cw]; wh2A[i] = c.x; wh2B[i] = c.y;
        }
    }
    float b1v = 0.f, b2v = 0.f;
    if (tid < 256) {
        b1v = b1[colg + (tid >> 2)];
        b2v = b2[colg + (tid >> 2)];
    }
    uint32_t su = s2u(sm);
    uint32_t peer[4];
#pragma unroll
    for (int r = 0; r < 4; r++)
        asm("mapa.shared::cluster.u32 %0,%1,%2;" : "=r"(peer[r]) : "r"(su), "r"(r));

    if (tid == 0) {
#pragma unroll
        for (int s = 0; s < 4; s++) {
            mbar_init(su + MB1_B + 8 * s, 1);
            mbar_init(su + MB2_B + 8 * s, 1);
        }
        // phase-0 expects, posted once before any sends exist
#pragma unroll
        for (int s = 0; s < 4; s++) {
            mbar_expect(su + MB1_B + 8 * s, 1024);
            mbar_expect(su + MB2_B + 8 * s, 1024);
        }
    }
    // stage x(0): xT[0][k*4+m]
    const size_t xbase = (size_t)(bm0 + (tid & 3)) * TT * DD + (tid >> 2);
    if (tid < 256) sm[OFF_XT + tid] = x[xbase];
    __syncthreads();
    CLUSTER_SYNC();   // mbarriers + expects + buffers live before any st.async

    // initial L1(0) partials (h1(-1) = zeros in parity-1 buffer)
    ull aA01 = 0, aA23 = 0, aB01 = 0, aB23 = 0;
    accum_x(sm + OFF_WX1, w, lane, (const float4*)(sm + OFF_XT) + 4 * w,
            aA01, aA23, aB01, aB23);
    accum16(wh1A, wh1B, (const float4*)(sm + OFF_H1 + 1024) + 16 * w, aA01, aA23, aB01, aB23);

#pragma unroll 1
    for (int t = 0; t < TT; t++) {
        int p = t & 1, pn = p ^ 1;
        // ---- phase A: finish layer 1, broadcast h1(t) ----
        reduce_bcast(sm, tid, w, lane, aA01, aA23, aB01, aB23, b1v,
                     OFF_H1 + p * 1024, colg, peer, MB1_B + 8 * rank);
        // per-warp wait: only this warp's h2 source slice (skip at t=0: zeros)
        if (t) {
            mbar_wait(su + MB2_B + src8, (uint32_t)((t - 1) & 1));
            if (owner) mbar_expect(su + MB2_B + src8, 1024);   // next phase, now safe
        }
        aA01 = 0; aA23 = 0; aB01 = 0; aB23 = 0;
        accum16(wh2A, wh2B, (const float4*)(sm + OFF_H2 + pn * 1024) + 16 * w,
                aA01, aA23, aB01, aB23);
        if (t + 1 < TT && tid < 256)
            sm[OFF_XT + pn * 256 + tid] = x[xbase + (size_t)(t + 1) * DD];

        // ---- phase B: Wx2*h1(t), finish layer 2, broadcast h2(t) ----
        mbar_wait(su + MB1_B + src8, (uint32_t)p);   // this warp's h1 source slice
        if (owner) mbar_expect(su + MB1_B + src8, 1024);       // next phase, now safe
        accum16(wx2A, wx2B, (const float4*)(sm + OFF_H1 + p * 1024) + 16 * w,
                aA01, aA23, aB01, aB23);
        reduce_bcast(sm, tid, w, lane, aA01, aA23, aB01, aB23, b2v,
                     OFF_H2 + p * 1024, colg, peer, MB2_B + 8 * rank);
        // hidden: L1(t+1) = Wx1*x(t+1) + Wh1*h1(t)  (h1 src already waited)
        aA01 = 0; aA23 = 0; aB01 = 0; aB23 = 0;
        if (t + 1 < TT) {
            accum_x(sm + OFF_WX1, w, lane, (const float4*)(sm + OFF_XT + pn * 256) + 4 * w,
                    aA01, aA23, aB01, aB23);
            accum16(wh1A, wh1B, (const float4*)(sm + OFF_H1 + p * 1024) + 16 * w,
                    aA01, aA23, aB01, aB23);
        }
    }
    // make final h2 (all 4 source slices, step-1023 phase parity = 1) visible
#pragma unroll
    for (int s = 0; s < 4; s++) mbar_wait(su + MB2_B + 8 * s, 1u);
    __syncthreads();

    // ---- epilogue: every rank outputs its own batch row (h2 replicated) ----
    {
        const float* h2f = sm + OFF_H2 + 1024;  // parity of t=1023 is 1
        int kq = tid >> 7, o = tid & 127;
        float part = 0.f;
#pragma unroll 8
        for (int i = 0; i < 64; i++) {
            int k = kq * 64 + i;
            part += h2f[k * 4 + rank] * Wd[k * OO + o];
        }
        sm[OFF_SCR + kq * 128 + o] = part;
        __syncthreads();
        if (tid < 128) {
            float l = bd[tid] + sm[OFF_SCR + tid] + sm[OFF_SCR + 128 + tid]
                    + sm[OFF_SCR + 256 + tid] + sm[OFF_SCR + 384 + tid];
            sm[OFF_SCR + 512 + tid] = l;
        }
        __syncthreads();
        if (tid < 32) {
            const float* L = sm + OFF_SCR + 512;
            float v0 = L[tid], v1 = L[tid + 32], v2 = L[tid + 64], v3 = L[tid + 96];
            float mx = fmaxf(fmaxf(v0, v1), fmaxf(v2, v3));
#pragma unroll
            for (int s = 16; s; s >>= 1) mx = fmaxf(mx, __shfl_xor_sync(0xffffffffu, mx, s));
            float e0 = __expf(v0 - mx), e1 = __expf(v1 - mx);
            float e2 = __expf(v2 - mx), e3 = __expf(v3 - mx);
            float ssum = e0 + e1 + e2 + e3;
#pragma unroll
            for (int s = 16; s; s >>= 1) ssum += __shfl_xor_sync(0xffffffffu, ssum, s);
            float inv = 1.f / ssum;
            float* orow = out + (size_t)(bm0 + (int)rank) * OO;
            orow[tid] = e0 * inv;
            orow[tid + 32] = e1 * inv;
            orow[tid + 64] = e2 * inv;
            orow[tid + 96] = e3 * inv;
        }
    }
    CLUSTER_SYNC();   // keep cluster alive until all in-flight st.async land
}

extern "C" void kernel_launch(void* const* d_in, const int* in_sizes, int n_in,
                              void* d_out, int out_size) {
    cudaFuncSetAttribute(rnn_kernel, cudaFuncAttributeMaxDynamicSharedMemorySize, SMEM_BYTES);
    rnn_kernel<<<128, THREADS, SMEM_BYTES>>>(
        (const float*)d_in[0], (const float*)d_in[1], (const float*)d_in[2],
        (const float*)d_in[3], (const float*)d_in[4], (const float*)d_in[5],
        (const float*)d_in[6], (const float*)d_in[7], (const float*)d_in[8],
        (float*)d_out);
}

// round 15
// speedup vs baseline: 1.1669x; 1.0610x over previous
#include <cuda_runtime.h>
#include <cstdint>

#define TT 1024
#define DD 64
#define HH 256
#define OO 128
#define THREADS 512

typedef unsigned long long ull;

// smem float offsets (dynamic) — R12 layout + phase-split scratch
#define OFF_WX1 0        // [64][64]   wx1[k*64 + jloc]
#define OFF_H1  4096     // [2][1024]  h1[p][col*4 + m]
#define OFF_H2  6144     // [2][1024]
#define OFF_XT  8192     // [2][256]   xT[p][k*4 + m]
#define OFF_SCRA 8704    // [16][256]  layer-1 reduction scratch
#define OFF_SCRB 12800   // [16][256]  layer-2 reduction scratch
#define OFF_MBAR 16896   // 8 x u64 mbarriers: mb1[0..3], mb2[0..3]
#define SMEM_FLOATS 16912
#define SMEM_BYTES (SMEM_FLOATS * 4)
#define MB1_B (OFF_MBAR * 4)          // mb1[s] = MB1_B + 8*s  (h1 exchange, per source)
#define MB2_B (OFF_MBAR * 4 + 32)     // mb2[s] = MB2_B + 8*s  (h2 exchange, per source)

__device__ __forceinline__ ull ffma2(ull a, ull b, ull c) {
    ull d; asm("fma.rn.f32x2 %0,%1,%2,%3;" : "=l"(d) : "l"(a), "l"(b), "l"(c)); return d;
}
__device__ __forceinline__ ull pk2(float lo, float hi) {
    ull d; asm("mov.b64 %0,{%1,%2};" : "=l"(d) : "f"(lo), "f"(hi)); return d;
}
__device__ __forceinline__ void up2(ull a, float& lo, float& hi) {
    asm("mov.b64 {%0,%1},%2;" : "=f"(lo), "=f"(hi) : "l"(a));
}
__device__ __forceinline__ uint32_t s2u(const void* p) {
    uint32_t a;
    asm("{.reg .u64 t; cvta.to.shared.u64 t, %1; cvt.u32.u64 %0, t;}" : "=r"(a) : "l"(p));
    return a;
}
__device__ __forceinline__ void mbar_init(uint32_t m, uint32_t cnt) {
    asm volatile("mbarrier.init.shared.b64 [%0], %1;" :: "r"(m), "r"(cnt) : "memory");
}
__device__ __forceinline__ void mbar_expect(uint32_t m, uint32_t bytes) {
    asm volatile("mbarrier.arrive.expect_tx.shared.b64 _, [%0], %1;" :: "r"(m), "r"(bytes) : "memory");
}
__device__ __forceinline__ void mbar_wait(uint32_t m, uint32_t parity) {
    asm volatile(
        "{\n\t.reg .pred P;\n"
        "W%=:\n\t"
        "mbarrier.try_wait.parity.acquire.cta.shared::cta.b64 P, [%0], %1, 0x989680;\n\t"
        "@!P bra W%=;\n\t}"
        :: "r"(m), "r"(parity) : "memory");
}
__device__ __forceinline__ void st_async_f32(uint32_t daddr, float v, uint32_t dmbar) {
    asm volatile("st.async.shared::cluster.mbarrier::complete_tx::bytes.f32 [%0], %1, [%2];"
                 :: "r"(daddr), "f"(v), "r"(dmbar) : "memory");
}
#define CLUSTER_SYNC() do { \
    asm volatile("barrier.cluster.arrive.aligned;" ::: "memory"); \
    asm volatile("barrier.cluster.wait.aligned;" ::: "memory"); } while (0)

// 16 k-steps vs register weights; hv = broadcast float4 rows h[k][m0..3] (R4/R12-proven)
__device__ __forceinline__ void accum16(const float (&wA)[16], const float (&wB)[16],
                                        const float4* __restrict__ hv,
                                        ull& aA01, ull& aA23, ull& aB01, ull& aB23) {
#pragma unroll
    for (int i = 0; i < 16; i++) {
        float4 h4 = hv[i];
        ull H01 = pk2(h4.x, h4.y), H23 = pk2(h4.z, h4.w);
        ull wdA = pk2(wA[i], wA[i]);
        ull wdB = pk2(wB[i], wB[i]);
        aA01 = ffma2(wdA, H01, aA01);
        aA23 = ffma2(wdA, H23, aA23);
        aB01 = ffma2(wdB, H01, aB01);
        aB23 = ffma2(wdB, H23, aB23);
    }
}

// 4 k-steps of x-projection; warp w covers k in [4w,4w+4). (R4/R12-proven)
__device__ __forceinline__ void accum_x(const float* __restrict__ smw, int w, int lane,
                                        const float4* __restrict__ xv,
                                        ull& aA01, ull& aA23, ull& aB01, ull& aB23) {
#pragma unroll
    for (int i = 0; i < 4; i++) {
        float2 wv = *(const float2*)(smw + (4 * w + i) * 64 + 2 * lane);
        float4 h4 = xv[i];
        ull H01 = pk2(h4.x, h4.y), H23 = pk2(h4.z, h4.w);
        ull wdA = pk2(wv.x, wv.x);
        ull wdB = pk2(wv.y, wv.y);
        aA01 = ffma2(wdA, H01, aA01);
        aA23 = ffma2(wdA, H23, aA23);
        aB01 = ffma2(wdB, H01, aB01);
        aB23 = ffma2(wdB, H23, aB23);
    }
}

// ONE-bar 16-way reduce (phase-owned scratch) + tree-sum + bias + tanh +
// f32 st.async broadcast completing the PER-SOURCE mbarrier on each dest.
__device__ __forceinline__ void reduce_bcast(float* sm, int tid, int w, int lane,
                                             ull aA01, ull aA23, ull aB01, ull aB23,
                                             float bias, int scr, int dst_off, int colg,
                                             const uint32_t (&peer)[4], uint32_t mbar_src_b) {
    float4 pA, pB;
    up2(aA01, pA.x, pA.y); up2(aA23, pA.z, pA.w);
    up2(aB01, pB.x, pB.y); up2(aB23, pB.z, pB.w);
    float4* base = (float4*)(sm + scr + w * 256 + 8 * lane);
    base[0] = pA;                              // outs [8*lane, 8*lane+8) dense
    base[1] = pB;
    __syncthreads();                           // single bar: partials visible
    if (tid < 256) {
        const float* s0 = sm + scr + tid;
        float t0 = s0[0 * 256] + s0[8 * 256];
        float t1 = s0[1 * 256] + s0[9 * 256];
        float t2 = s0[2 * 256] + s0[10 * 256];
        float t3 = s0[3 * 256] + s0[11 * 256];
        float t4 = s0[4 * 256] + s0[12 * 256];
        float t5 = s0[5 * 256] + s0[13 * 256];
        float t6 = s0[6 * 256] + s0[14 * 256];
        float t7 = s0[7 * 256] + s0[15 * 256];
        t0 += t4; t1 += t5; t2 += t6; t3 += t7;
        float h = tanhf(((t0 + t2) + (t1 + t3)) + bias);
        uint32_t off = (uint32_t)(dst_off + colg * 4 + tid) * 4u;
#pragma unroll
        for (int r = 0; r < 4; r++)
            st_async_f32(peer[r] + off, h, peer[r] + mbar_src_b);
    }
}

__global__ void __launch_bounds__(THREADS, 1) __cluster_dims__(4, 1, 1)
rnn_kernel(const float* __restrict__ x, const float* __restrict__ Wx1,
           const float* __restrict__ Wh1, const float* __restrict__ b1,
           const float* __restrict__ Wx2, const float* __restrict__ Wh2,
           const float* __restrict__ b2, const float* __restrict__ Wd,
           const float* __restrict__ bd, float* __restrict__ out) {
    extern __shared__ float sm[];
    int tid = threadIdx.x;
    int w = tid >> 5, lane = tid & 31;
    uint32_t rank;
    asm("mov.u32 %0, %%cluster_ctarank;" : "=r"(rank));
    int colg = (int)rank * 64;
    int bm0 = ((int)blockIdx.x >> 2) * 4;
    uint32_t src8 = 8u * (uint32_t)(w >> 2);        // this warp's h-source CTA * 8
    bool owner = ((w & 3) == 0) && (lane == 0);     // one poster per source barrier

    // Wx1 slice -> smem (k-major, 64 cols of this CTA)
    for (int i = tid; i < 4096; i += THREADS) {
        int k = i >> 6, jl = i & 63;
        sm[OFF_WX1 + i] = Wx1[k * HH + colg + jl];
    }
    // zero h buffers + xT
    for (int i = tid; i < 4608; i += THREADS) sm[OFF_H1 + i] = 0.f;

    // recurrent weights -> registers: warp w owns k in [16w,16w+16),
    // lane owns cols {colg+2*lane, colg+2*lane+1}
    float wh1A[16], wh1B[16], wx2A[16], wx2B[16], wh2A[16], wh2B[16];
    {
        const float2* g1 = (const float2*)Wh1;
        const float2* g2 = (const float2*)Wx2;
        const float2* g3 = (const float2*)Wh2;
        int cw = (colg >> 1) + lane;
#pragma unroll
        for (int i = 0; i < 16; i++) {
            float2 a = g1[(16 * w + i) * (HH / 2) + cw]; wh1A[i] = a.x; wh1B[i] = a.y;
            float2 b = g2[(16 * w + i) * (HH / 2) + cw]; wx2A[i] = b.x; wx2B[i] = b.y;
            float2 c = g3[(16 * w + i) * (HH / 2) + cw]; wh2A[i] = c.x; wh2B[i] = c.y;
        }
    }
    float b1v = 0.f, b2v = 0.f;
    if (tid < 256) {
        b1v = b1[colg + (tid >> 2)];
        b2v = b2[colg + (tid >> 2)];
    }
    uint32_t su = s2u(sm);
    uint32_t peer[4];
#pragma unroll
    for (int r = 0; r < 4; r++)
        asm("mapa.shared::cluster.u32 %0,%1,%2;" : "=r"(peer[r]) : "r"(su), "r"(r));

    if (tid == 0) {
#pragma unroll
        for (int s = 0; s < 4; s++) {
            mbar_init(su + MB1_B + 8 * s, 1);
            mbar_init(su + MB2_B + 8 * s, 1);
        }
        // phase-0 expects, posted once before any sends exist
#pragma unroll
        for (int s = 0; s < 4; s++) {
            mbar_expect(su + MB1_B + 8 * s, 1024);
            mbar_expect(su + MB2_B + 8 * s, 1024);
        }
    }
    // stage x(0): xT[0][k*4+m]
    const size_t xbase = (size_t)(bm0 + (tid & 3)) * TT * DD + (tid >> 2);
    if (tid < 256) sm[OFF_XT + tid] = x[xbase];
    __syncthreads();
    CLUSTER_SYNC();   // mbarriers + expects + buffers live before any st.async

    // initial L1(0) partials (h1(-1) = zeros in parity-1 buffer)
    ull aA01 = 0, aA23 = 0, aB01 = 0, aB23 = 0;
    accum_x(sm + OFF_WX1, w, lane, (const float4*)(sm + OFF_XT) + 4 * w,
            aA01, aA23, aB01, aB23);
    accum16(wh1A, wh1B, (const float4*)(sm + OFF_H1 + 1024) + 16 * w, aA01, aA23, aB01, aB23);

#pragma unroll 1
    for (int t = 0; t < TT; t++) {
        int p = t & 1, pn = p ^ 1;
        // ---- phase A: finish layer 1, broadcast h1(t) ----
        reduce_bcast(sm, tid, w, lane, aA01, aA23, aB01, aB23, b1v,
                     OFF_SCRA, OFF_H1 + p * 1024, colg, peer, MB1_B + 8 * rank);
        // per-warp wait: only this warp's h2 source slice (skip at t=0: zeros)
        if (t) {
            mbar_wait(su + MB2_B + src8, (uint32_t)((t - 1) & 1));
            if (owner) mbar_expect(su + MB2_B + src8, 1024);   // next phase, now safe
        }
        aA01 = 0; aA23 = 0; aB01 = 0; aB23 = 0;
        accum16(wh2A, wh2B, (const float4*)(sm + OFF_H2 + pn * 1024) + 16 * w,
                aA01, aA23, aB01, aB23);
        if (t + 1 < TT && tid < 256)
            sm[OFF_XT + pn * 256 + tid] = x[xbase + (size_t)(t + 1) * DD];

        // ---- phase B: Wx2*h1(t), finish layer 2, broadcast h2(t) ----
        mbar_wait(su + MB1_B + src8, (uint32_t)p);   // this warp's h1 source slice
        if (owner) mbar_expect(su + MB1_B + src8, 1024);       // next phase, now safe
        accum16(wx2A, wx2B, (const float4*)(sm + OFF_H1 + p * 1024) + 16 * w,
                aA01, aA23, aB01, aB23);
        reduce_bcast(sm, tid, w, lane, aA01, aA23, aB01, aB23, b2v,
                     OFF_SCRB, OFF_H2 + p * 1024, colg, peer, MB2_B + 8 * rank);
        // hidden: L1(t+1) = Wx1*x(t+1) + Wh1*h1(t)  (h1 src already waited)
        aA01 = 0; aA23 = 0; aB01 = 0; aB23 = 0;
        if (t + 1 < TT) {
            accum_x(sm + OFF_WX1, w, lane, (const float4*)(sm + OFF_XT + pn * 256) + 4 * w,
                    aA01, aA23, aB01, aB23);
            accum16(wh1A, wh1B, (const float4*)(sm + OFF_H1 + p * 1024) + 16 * w,
                    aA01, aA23, aB01, aB23);
        }
    }
    // make final h2 (all 4 source slices, step-1023 phase parity = 1) visible
#pragma unroll
    for (int s = 0; s < 4; s++) mbar_wait(su + MB2_B + 8 * s, 1u);
    __syncthreads();

    // ---- epilogue: every rank outputs its own batch row (h2 replicated) ----
    {
        const float* h2f = sm + OFF_H2 + 1024;  // parity of t=1023 is 1
        int kq = tid >> 7, o = tid & 127;
        float part = 0.f;
#pragma unroll 8
        for (int i = 0; i < 64; i++) {
            int k = kq * 64 + i;
            part += h2f[k * 4 + rank] * Wd[k * OO + o];
        }
        sm[OFF_SCRA + kq * 128 + o] = part;
        __syncthreads();
        if (tid < 128) {
            float l = bd[tid] + sm[OFF_SCRA + tid] + sm[OFF_SCRA + 128 + tid]
                    + sm[OFF_SCRA + 256 + tid] + sm[OFF_SCRA + 384 + tid];
            sm[OFF_SCRA + 512 + tid] = l;
        }
        __syncthreads();
        if (tid < 32) {
            const float* L = sm + OFF_SCRA + 512;
            float v0 = L[tid], v1 = L[tid + 32], v2 = L[tid + 64], v3 = L[tid + 96];
            float mx = fmaxf(fmaxf(v0, v1), fmaxf(v2, v3));
#pragma unroll
            for (int s = 16; s; s >>= 1) mx = fmaxf(mx, __shfl_xor_sync(0xffffffffu, mx, s));
            float e0 = __expf(v0 - mx), e1 = __expf(v1 - mx);
            float e2 = __expf(v2 - mx), e3 = __expf(v3 - mx);
            float ssum = e0 + e1 + e2 + e3;
#pragma unroll
            for (int s = 16; s; s >>= 1) ssum += __shfl_xor_sync(0xffffffffu, ssum, s);
            float inv = 1.f / ssum;
            float* orow = out + (size_t)(bm0 + (int)rank) * OO;
            orow[tid] = e0 * inv;
            orow[tid + 32] = e1 * inv;
            orow[tid + 64] = e2 * inv;
            orow[tid + 96] = e3 * inv;
        }
    }
    CLUSTER_SYNC();   // keep cluster alive until all in-flight st.async land
}

extern "C" void kernel_launch(void* const* d_in, const int* in_sizes, int n_in,
                              void* d_out, int out_size) {
    cudaFuncSetAttribute(rnn_kernel, cudaFuncAttributeMaxDynamicSharedMemorySize, SMEM_BYTES);
    rnn_kernel<<<128, THREADS, SMEM_BYTES>>>(
        (const float*)d_in[0], (const float*)d_in[1], (const float*)d_in[2],
        (const float*)d_in[3], (const float*)d_in[4], (const float*)d_in[5],
        (const float*)d_in[6], (const float*)d_in[7], (const float*)d_in[8],
        (float*)d_out);
}